// round 8
// baseline (speedup 1.0000x reference)
#include <cuda_runtime.h>
#include <cstdint>
#include <cstddef>

#define D_MODEL 1024
#define NH      16
#define DH      64
#define BB      4
#define TT      2048
#define BT      (BB * TT)

__device__ float g_qkv[(size_t)BT * 3 * D_MODEL];   // [B*T, 3072]
__device__ float g_y  [(size_t)BT * D_MODEL];       // [B*T, 1024]

// ---------------------------------------------------------------------------
__device__ __forceinline__ uint32_t f2tf(float x) {
    uint32_t u;
    asm("cvt.rna.tf32.f32 %0, %1;" : "=r"(u) : "f"(x));
    return u;
}

__device__ __forceinline__ void mma_tf32(float c[4], const uint32_t a[4],
                                         const uint32_t b[2]) {
    asm volatile(
        "mma.sync.aligned.m16n8k8.row.col.f32.tf32.tf32.f32 "
        "{%0,%1,%2,%3},{%4,%5,%6,%7},{%8,%9},{%0,%1,%2,%3};"
        : "+f"(c[0]), "+f"(c[1]), "+f"(c[2]), "+f"(c[3])
        : "r"(a[0]), "r"(a[1]), "r"(a[2]), "r"(a[3]), "r"(b[0]), "r"(b[1]));
}

// ---------------------------------------------------------------------------
// TF32 GEMM (round-5 known-good): C[M,N] = A[M,K] * B[N,K]^T.
// 128x128 block, 8 warps (64x32 each), K-chunk 32.
// Coalesced LDG + XOR-swizzled fragment-order smem (conflict-free STS/LDS).
// ---------------------------------------------------------------------------
__global__ __launch_bounds__(256)
void gemm_tf32(const float* __restrict__ A, const float* __restrict__ Bw,
               float* __restrict__ C, int M, int N, int K) {
    __shared__ __align__(16) uint32_t As[8 * 4 * 4 * 32];
    __shared__ __align__(16) uint32_t Bs[16 * 4 * 2 * 32];

    const int tid    = threadIdx.x;
    const int lane   = tid & 31;
    const int wid    = tid >> 5;
    const int warp_m = wid >> 2;
    const int warp_n = wid & 3;
    const int m0     = blockIdx.y * 128;
    const int n0     = blockIdx.x * 128;

    float acc[4][4][4];
    #pragma unroll
    for (int i = 0; i < 4; i++)
        #pragma unroll
        for (int j = 0; j < 4; j++)
            #pragma unroll
            for (int r = 0; r < 4; r++) acc[i][j][r] = 0.f;

    for (int k0 = 0; k0 < K; k0 += 32) {
        #pragma unroll
        for (int it = 0; it < 4; it++) {
            int lin = tid + it * 256;
            int row = lin >> 3;
            int q   = lin & 7;
            float4 v = *(const float4*)&A[(size_t)(m0 + row) * K + k0 + q * 4];
            int off = ((((row >> 4) * 4 + (q >> 1)) * 4 + (((row >> 3) & 1) + 2 * (q & 1))) << 5)
                      + ((((row & 7) << 2)) ^ (q << 2));
            *(uint4*)&As[off] = make_uint4(f2tf(v.x), f2tf(v.y), f2tf(v.z), f2tf(v.w));
        }
        #pragma unroll
        for (int it = 0; it < 4; it++) {
            int lin = tid + it * 256;
            int row = lin >> 3;
            int q   = lin & 7;
            float4 v = *(const float4*)&Bw[(size_t)(n0 + row) * K + k0 + q * 4];
            int off = ((((row >> 3) * 4 + (q >> 1)) * 2 + (q & 1)) << 5)
                      + ((((row & 7) << 2)) ^ (q << 2));
            *(uint4*)&Bs[off] = make_uint4(f2tf(v.x), f2tf(v.y), f2tf(v.z), f2tf(v.w));
        }
        __syncthreads();

        #pragma unroll
        for (int ks = 0; ks < 4; ks++) {
            uint32_t af[4][4], bf[4][2];
            #pragma unroll
            for (int i = 0; i < 4; i++) {
                int base = ((warp_m * 4 + i) * 4 + ks) * 4 * 32;
                #pragma unroll
                for (int aidx = 0; aidx < 4; aidx++) {
                    int q = 2 * ks + (aidx >> 1);
                    af[i][aidx] = As[base + aidx * 32 + (lane ^ (q << 2))];
                }
            }
            #pragma unroll
            for (int j = 0; j < 4; j++) {
                int base = ((warp_n * 4 + j) * 4 + ks) * 2 * 32;
                #pragma unroll
                for (int p = 0; p < 2; p++) {
                    int q = 2 * ks + p;
                    bf[j][p] = Bs[base + p * 32 + (lane ^ (q << 2))];
                }
            }
            #pragma unroll
            for (int i = 0; i < 4; i++)
                #pragma unroll
                for (int j = 0; j < 4; j++)
                    mma_tf32(acc[i][j], af[i], bf[j]);
        }
        __syncthreads();
    }

    const int g = lane >> 2, t = lane & 3;
    #pragma unroll
    for (int i = 0; i < 4; i++) {
        int rbase = m0 + warp_m * 64 + i * 16 + g;
        #pragma unroll
        for (int j = 0; j < 4; j++) {
            int cbase = n0 + warp_n * 32 + j * 8 + t * 2;
            *(float2*)&C[(size_t)rbase * N + cbase] =
                make_float2(acc[i][j][0], acc[i][j][1]);
            *(float2*)&C[(size_t)(rbase + 8) * N + cbase] =
                make_float2(acc[i][j][2], acc[i][j][3]);
        }
    }
}

// ---------------------------------------------------------------------------
// Tensor-core flash attention v3 (tf32, mma.sync).
// 4 warps x 32 queries = 128 queries/block. Two 16-row groups per warp share
// every K/V B-fragment load (halves LDS per MMA and staging per query).
// ---------------------------------------------------------------------------
__global__ __launch_bounds__(128)
void attn_tc() {
    __shared__ __align__(16) uint32_t Kf[8 * 8 * 2 * 32];
    __shared__ __align__(16) uint32_t Vf[8 * 8 * 2 * 32];

    const int tid  = threadIdx.x;
    const int lane = tid & 31;
    const int w    = tid >> 5;
    const int g    = lane >> 2;
    const int t    = lane & 3;
    const int qt   = blockIdx.x;      // 128-query tile
    const int h    = blockIdx.y;
    const int b    = blockIdx.z;

    const size_t base = (size_t)b * TT * (3 * D_MODEL);
    const int    hcol = h * DH;
    const int    q0   = qt * 128 + w * 32;

    // Q fragments for both row groups
    uint32_t qfA[8][4], qfB[8][4];
    {
        const float* r0 = g_qkv + base + (size_t)(q0 + g) * (3 * D_MODEL) + hcol;
        const float* r8 = r0 + (size_t)8 * (3 * D_MODEL);
        const float* r16 = r0 + (size_t)16 * (3 * D_MODEL);
        const float* r24 = r0 + (size_t)24 * (3 * D_MODEL);
        #pragma unroll
        for (int kg = 0; kg < 8; kg++) {
            qfA[kg][0] = f2tf(r0 [kg * 8 + t]);
            qfA[kg][1] = f2tf(r8 [kg * 8 + t]);
            qfA[kg][2] = f2tf(r0 [kg * 8 + t + 4]);
            qfA[kg][3] = f2tf(r8 [kg * 8 + t + 4]);
            qfB[kg][0] = f2tf(r16[kg * 8 + t]);
            qfB[kg][1] = f2tf(r24[kg * 8 + t]);
            qfB[kg][2] = f2tf(r16[kg * 8 + t + 4]);
            qfB[kg][3] = f2tf(r24[kg * 8 + t + 4]);
        }
    }

    float mA0 = -1e30f, mA1 = -1e30f, lA0 = 0.f, lA1 = 0.f;
    float mB0 = -1e30f, mB1 = -1e30f, lB0 = 0.f, lB1 = 0.f;
    float oA[8][4], oB[8][4];
    #pragma unroll
    for (int nt = 0; nt < 8; nt++)
        #pragma unroll
        for (int e = 0; e < 4; e++) { oA[nt][e] = 0.f; oB[nt][e] = 0.f; }

    const int src  = (lane & ~3) | (t >> 1);
    const int src2 = src + 2;

    const int jmax = 2 * qt + 1;
    for (int j = 0; j <= jmax; j++) {
        __syncthreads();
        // ---- stage K, V tiles (64 keys x 64 d), 128 threads ----
        #pragma unroll
        for (int it = 0; it < 8; it++) {
            int lin = tid + it * 128;
            int key = (lin & 7) | ((lin >> 7) << 3);
            int c   = (lin >> 3) & 15;
            const float* kvp = g_qkv + base + (size_t)(j * 64 + key) * (3 * D_MODEL)
                               + D_MODEL + hcol + c * 4;
            float4 kv4 = *(const float4*)kvp;
            float4 vv4 = *(const float4*)(kvp + D_MODEL);

            int koff = (((((c >> 1) * 8 + (key >> 3)) * 2) + (c & 1)) << 5) + ((key & 7) << 2);
            *(uint4*)&Kf[koff] = make_uint4(f2tf(kv4.x), f2tf(kv4.y), f2tf(kv4.z), f2tf(kv4.w));

            int kgv  = key >> 3;
            int pv   = (key >> 2) & 1;
            int ntv  = c >> 1;
            int vb   = ((kgv * 8 + ntv) * 2 + pv) << 5;
            int lb   = 16 * (c & 1) + (key & 3);
            int swz  = (4 * (ntv & 1)) ^ (8 * pv);
            float ve[4] = {vv4.x, vv4.y, vv4.z, vv4.w};
            #pragma unroll
            for (int jj = 0; jj < 4; jj++)
                Vf[vb + ((lb + 4 * jj) ^ swz)] = f2tf(ve[jj]);
        }
        __syncthreads();

        const int off  = q0 - j * 64;       // group A rows: off..off+15 vs keys 0..63
        const int relA = off + 15;
        const int relB = off + 31;
        const int limA = (relA < 0) ? 0 : ((relA >> 3) + 1 > 8 ? 8 : (relA >> 3) + 1);
        const int limB = (relB < 0) ? 0 : ((relB >> 3) + 1 > 8 ? 8 : (relB >> 3) + 1);
        if (limB == 0) continue;
        const bool maskA = (off < 63);
        const bool maskB = (off + 16 < 63);

        // ---- S = Q K^T (shared bf for both groups) ----
        float sA[8][4], sB[8][4];
        #pragma unroll
        for (int nt = 0; nt < 8; nt++) {
            if (nt < limB) {
                #pragma unroll
                for (int e = 0; e < 4; e++) { sA[nt][e] = 0.f; sB[nt][e] = 0.f; }
                #pragma unroll
                for (int kg = 0; kg < 8; kg++) {
                    int kb = ((kg * 8 + nt) * 2) << 5;
                    uint32_t bf[2] = {Kf[kb + lane], Kf[kb + 32 + lane]};
                    if (nt < limA) mma_tf32(sA[nt], qfA[kg], bf);
                    mma_tf32(sB[nt], qfB[kg], bf);
                }
            }
        }

        // ---- scale + causal mask ----
        #pragma unroll
        for (int nt = 0; nt < 8; nt++) {
            if (nt < limB) {
                #pragma unroll
                for (int e = 0; e < 4; e++) {
                    int keyl = nt * 8 + 2 * t + (e & 1);
                    int rbase2 = off + g + ((e >> 1) << 3);
                    if (nt < limA) {
                        float v = sA[nt][e] * 0.125f;
                        if (maskA && keyl > rbase2) v = -1e30f;
                        sA[nt][e] = v;
                    }
                    float v = sB[nt][e] * 0.125f;
                    if (maskB && keyl > rbase2 + 16) v = -1e30f;
                    sB[nt][e] = v;
                }
            }
        }

        // ---- online softmax, group A ----
        if (limA > 0) {
            float rm0 = -1e30f, rm1 = -1e30f;
            #pragma unroll
            for (int nt = 0; nt < 8; nt++) {
                if (nt < limA) {
                    rm0 = fmaxf(rm0, fmaxf(sA[nt][0], sA[nt][1]));
                    rm1 = fmaxf(rm1, fmaxf(sA[nt][2], sA[nt][3]));
                }
            }
            rm0 = fmaxf(rm0, __shfl_xor_sync(0xffffffffu, rm0, 1));
            rm0 = fmaxf(rm0, __shfl_xor_sync(0xffffffffu, rm0, 2));
            rm1 = fmaxf(rm1, __shfl_xor_sync(0xffffffffu, rm1, 1));
            rm1 = fmaxf(rm1, __shfl_xor_sync(0xffffffffu, rm1, 2));
            float mn0 = fmaxf(mA0, rm0), mn1 = fmaxf(mA1, rm1);
            float a0 = __expf(mA0 - mn0), a1 = __expf(mA1 - mn1);
            mA0 = mn0; mA1 = mn1;
            float rs0 = 0.f, rs1 = 0.f;
            #pragma unroll
            for (int nt = 0; nt < 8; nt++) {
                if (nt < limA) {
                    sA[nt][0] = __expf(sA[nt][0] - mn0);
                    sA[nt][1] = __expf(sA[nt][1] - mn0);
                    sA[nt][2] = __expf(sA[nt][2] - mn1);
                    sA[nt][3] = __expf(sA[nt][3] - mn1);
                    rs0 += sA[nt][0] + sA[nt][1];
                    rs1 += sA[nt][2] + sA[nt][3];
                }
            }
            rs0 += __shfl_xor_sync(0xffffffffu, rs0, 1);
            rs0 += __shfl_xor_sync(0xffffffffu, rs0, 2);
            rs1 += __shfl_xor_sync(0xffffffffu, rs1, 1);
            rs1 += __shfl_xor_sync(0xffffffffu, rs1, 2);
            lA0 = lA0 * a0 + rs0;
            lA1 = lA1 * a1 + rs1;
            #pragma unroll
            for (int nt = 0; nt < 8; nt++) {
                oA[nt][0] *= a0; oA[nt][1] *= a0;
                oA[nt][2] *= a1; oA[nt][3] *= a1;
            }
        }
        // ---- online softmax, group B ----
        {
            float rm0 = -1e30f, rm1 = -1e30f;
            #pragma unroll
            for (int nt = 0; nt < 8; nt++) {
                if (nt < limB) {
                    rm0 = fmaxf(rm0, fmaxf(sB[nt][0], sB[nt][1]));
                    rm1 = fmaxf(rm1, fmaxf(sB[nt][2], sB[nt][3]));
                }
            }
            rm0 = fmaxf(rm0, __shfl_xor_sync(0xffffffffu, rm0, 1));
            rm0 = fmaxf(rm0, __shfl_xor_sync(0xffffffffu, rm0, 2));
            rm1 = fmaxf(rm1, __shfl_xor_sync(0xffffffffu, rm1, 1));
            rm1 = fmaxf(rm1, __shfl_xor_sync(0xffffffffu, rm1, 2));
            float mn0 = fmaxf(mB0, rm0), mn1 = fmaxf(mB1, rm1);
            float a0 = __expf(mB0 - mn0), a1 = __expf(mB1 - mn1);
            mB0 = mn0; mB1 = mn1;
            float rs0 = 0.f, rs1 = 0.f;
            #pragma unroll
            for (int nt = 0; nt < 8; nt++) {
                if (nt < limB) {
                    sB[nt][0] = __expf(sB[nt][0] - mn0);
                    sB[nt][1] = __expf(sB[nt][1] - mn0);
                    sB[nt][2] = __expf(sB[nt][2] - mn1);
                    sB[nt][3] = __expf(sB[nt][3] - mn1);
                    rs0 += sB[nt][0] + sB[nt][1];
                    rs1 += sB[nt][2] + sB[nt][3];
                }
            }
            rs0 += __shfl_xor_sync(0xffffffffu, rs0, 1);
            rs0 += __shfl_xor_sync(0xffffffffu, rs0, 2);
            rs1 += __shfl_xor_sync(0xffffffffu, rs1, 1);
            rs1 += __shfl_xor_sync(0xffffffffu, rs1, 2);
            lB0 = lB0 * a0 + rs0;
            lB1 = lB1 * a1 + rs1;
            #pragma unroll
            for (int nt = 0; nt < 8; nt++) {
                oB[nt][0] *= a0; oB[nt][1] *= a0;
                oB[nt][2] *= a1; oB[nt][3] *= a1;
            }
        }

        // ---- P: cvt + C-layout -> A-layout via shfl ----
        uint32_t pA[8][4], pB[8][4];
        #pragma unroll
        for (int kg = 0; kg < 8; kg++) {
            if (kg < limB) {
                bool odd = (t & 1);
                if (kg < limA) {
                    uint32_t c0 = f2tf(sA[kg][0]), c1 = f2tf(sA[kg][1]);
                    uint32_t c2 = f2tf(sA[kg][2]), c3 = f2tf(sA[kg][3]);
                    uint32_t u0 = __shfl_sync(0xffffffffu, c0, src);
                    uint32_t u1 = __shfl_sync(0xffffffffu, c1, src);
                    uint32_t u2 = __shfl_sync(0xffffffffu, c2, src);
                    uint32_t u3 = __shfl_sync(0xffffffffu, c3, src);
                    uint32_t v0 = __shfl_sync(0xffffffffu, c0, src2);
                    uint32_t v1 = __shfl_sync(0xffffffffu, c1, src2);
                    uint32_t v2 = __shfl_sync(0xffffffffu, c2, src2);
                    uint32_t v3 = __shfl_sync(0xffffffffu, c3, src2);
                    pA[kg][0] = odd ? u1 : u0;
                    pA[kg][1] = odd ? u3 : u2;
                    pA[kg][2] = odd ? v1 : v0;
                    pA[kg][3] = odd ? v3 : v2;
                }
                {
                    uint32_t c0 = f2tf(sB[kg][0]), c1 = f2tf(sB[kg][1]);
                    uint32_t c2 = f2tf(sB[kg][2]), c3 = f2tf(sB[kg][3]);
                    uint32_t u0 = __shfl_sync(0xffffffffu, c0, src);
                    uint32_t u1 = __shfl_sync(0xffffffffu, c1, src);
                    uint32_t u2 = __shfl_sync(0xffffffffu, c2, src);
                    uint32_t u3 = __shfl_sync(0xffffffffu, c3, src);
                    uint32_t v0 = __shfl_sync(0xffffffffu, c0, src2);
                    uint32_t v1 = __shfl_sync(0xffffffffu, c1, src2);
                    uint32_t v2 = __shfl_sync(0xffffffffu, c2, src2);
                    uint32_t v3 = __shfl_sync(0xffffffffu, c3, src2);
                    pB[kg][0] = odd ? u1 : u0;
                    pB[kg][1] = odd ? u3 : u2;
                    pB[kg][2] = odd ? v1 : v0;
                    pB[kg][3] = odd ? v3 : v2;
                }
            }
        }

        // ---- O += P V (shared bf for both groups) ----
        #pragma unroll
        for (int nt = 0; nt < 8; nt++) {          // d groups
            int sw0 = 4 * (nt & 1);
            #pragma unroll
            for (int kg = 0; kg < 8; kg++) {      // key groups
                if (kg < limB) {
                    int vb = ((kg * 8 + nt) * 2) << 5;
                    uint32_t bf[2] = {Vf[vb + (lane ^ sw0)],
                                      Vf[vb + 32 + (lane ^ sw0 ^ 8)]};
                    if (kg < limA) mma_tf32(oA[nt], pA[kg], bf);
                    mma_tf32(oB[nt], pB[kg], bf);
                }
            }
        }
    }

    // ---- epilogue: both groups ----
    {
        float i0 = 1.f / lA0, i1 = 1.f / lA1;
        size_t r0 = (size_t)(b * TT + q0 + g) * D_MODEL + hcol;
        size_t r1 = (size_t)(b * TT + q0 + g + 8) * D_MODEL + hcol;
        #pragma unroll
        for (int nt = 0; nt < 8; nt++) {
            int cb = nt * 8 + 2 * t;
            *(float2*)&g_y[r0 + cb] = make_float2(oA[nt][0] * i0, oA[nt][1] * i0);
            *(float2*)&g_y[r1 + cb] = make_float2(oA[nt][2] * i1, oA[nt][3] * i1);
        }
    }
    {
        float i0 = 1.f / lB0, i1 = 1.f / lB1;
        size_t r0 = (size_t)(b * TT + q0 + 16 + g) * D_MODEL + hcol;
        size_t r1 = (size_t)(b * TT + q0 + 24 + g) * D_MODEL + hcol;
        #pragma unroll
        for (int nt = 0; nt < 8; nt++) {
            int cb = nt * 8 + 2 * t;
            *(float2*)&g_y[r0 + cb] = make_float2(oB[nt][0] * i0, oB[nt][1] * i0);
            *(float2*)&g_y[r1 + cb] = make_float2(oB[nt][2] * i1, oB[nt][3] * i1);
        }
    }
}

// ---------------------------------------------------------------------------
extern "C" void kernel_launch(void* const* d_in, const int* in_sizes, int n_in,
                              void* d_out, int out_size) {
    const float* x      = (const float*)d_in[0];
    const float* w_qkv  = (const float*)d_in[1];
    const float* w_proj = (const float*)d_in[2];
    float*       out    = (float*)d_out;

    float *qkv_ptr = nullptr, *y_ptr = nullptr;
    cudaGetSymbolAddress((void**)&qkv_ptr, g_qkv);
    cudaGetSymbolAddress((void**)&y_ptr,   g_y);

    gemm_tf32<<<dim3(3 * D_MODEL / 128, BT / 128), 256>>>(x, w_qkv, qkv_ptr,
                                                          BT, 3 * D_MODEL, D_MODEL);

    attn_tc<<<dim3(TT / 128, NH, BB), 128>>>();

    gemm_tf32<<<dim3(D_MODEL / 128, BT / 128), 256>>>(y_ptr, w_proj, out,
                                                      BT, D_MODEL, D_MODEL);
}

// round 9
// speedup vs baseline: 1.5927x; 1.5927x over previous
#include <cuda_runtime.h>
#include <cstdint>
#include <cstddef>

#define D_MODEL 1024
#define NH      16
#define DH      64
#define BB      4
#define TT      2048
#define BT      (BB * TT)

__device__ float g_qkv[(size_t)BT * 3 * D_MODEL];   // [B*T, 3072]
__device__ float g_y  [(size_t)BT * D_MODEL];       // [B*T, 1024]

// ---------------------------------------------------------------------------
__device__ __forceinline__ uint32_t f2tf(float x) {
    uint32_t u;
    asm("cvt.rna.tf32.f32 %0, %1;" : "=r"(u) : "f"(x));
    return u;
}

__device__ __forceinline__ void mma_tf32(float c[4], const uint32_t a[4],
                                         const uint32_t b[2]) {
    asm volatile(
        "mma.sync.aligned.m16n8k8.row.col.f32.tf32.tf32.f32 "
        "{%0,%1,%2,%3},{%4,%5,%6,%7},{%8,%9},{%0,%1,%2,%3};"
        : "+f"(c[0]), "+f"(c[1]), "+f"(c[2]), "+f"(c[3])
        : "r"(a[0]), "r"(a[1]), "r"(a[2]), "r"(a[3]), "r"(b[0]), "r"(b[1]));
}

// ---------------------------------------------------------------------------
// TF32 GEMM (round-5 known-good): C[M,N] = A[M,K] * B[N,K]^T.
// 128x128 block, 8 warps (64x32 each), K-chunk 32.
// Coalesced LDG + XOR-swizzled fragment-order smem (conflict-free STS/LDS).
// ---------------------------------------------------------------------------
__global__ __launch_bounds__(256)
void gemm_tf32(const float* __restrict__ A, const float* __restrict__ Bw,
               float* __restrict__ C, int M, int N, int K) {
    __shared__ __align__(16) uint32_t As[8 * 4 * 4 * 32];
    __shared__ __align__(16) uint32_t Bs[16 * 4 * 2 * 32];

    const int tid    = threadIdx.x;
    const int lane   = tid & 31;
    const int wid    = tid >> 5;
    const int warp_m = wid >> 2;
    const int warp_n = wid & 3;
    const int m0     = blockIdx.y * 128;
    const int n0     = blockIdx.x * 128;

    float acc[4][4][4];
    #pragma unroll
    for (int i = 0; i < 4; i++)
        #pragma unroll
        for (int j = 0; j < 4; j++)
            #pragma unroll
            for (int r = 0; r < 4; r++) acc[i][j][r] = 0.f;

    for (int k0 = 0; k0 < K; k0 += 32) {
        #pragma unroll
        for (int it = 0; it < 4; it++) {
            int lin = tid + it * 256;
            int row = lin >> 3;
            int q   = lin & 7;
            float4 v = *(const float4*)&A[(size_t)(m0 + row) * K + k0 + q * 4];
            int off = ((((row >> 4) * 4 + (q >> 1)) * 4 + (((row >> 3) & 1) + 2 * (q & 1))) << 5)
                      + ((((row & 7) << 2)) ^ (q << 2));
            *(uint4*)&As[off] = make_uint4(f2tf(v.x), f2tf(v.y), f2tf(v.z), f2tf(v.w));
        }
        #pragma unroll
        for (int it = 0; it < 4; it++) {
            int lin = tid + it * 256;
            int row = lin >> 3;
            int q   = lin & 7;
            float4 v = *(const float4*)&Bw[(size_t)(n0 + row) * K + k0 + q * 4];
            int off = ((((row >> 3) * 4 + (q >> 1)) * 2 + (q & 1)) << 5)
                      + ((((row & 7) << 2)) ^ (q << 2));
            *(uint4*)&Bs[off] = make_uint4(f2tf(v.x), f2tf(v.y), f2tf(v.z), f2tf(v.w));
        }
        __syncthreads();

        #pragma unroll
        for (int ks = 0; ks < 4; ks++) {
            uint32_t af[4][4], bf[4][2];
            #pragma unroll
            for (int i = 0; i < 4; i++) {
                int base = ((warp_m * 4 + i) * 4 + ks) * 4 * 32;
                #pragma unroll
                for (int aidx = 0; aidx < 4; aidx++) {
                    int q = 2 * ks + (aidx >> 1);
                    af[i][aidx] = As[base + aidx * 32 + (lane ^ (q << 2))];
                }
            }
            #pragma unroll
            for (int j = 0; j < 4; j++) {
                int base = ((warp_n * 4 + j) * 4 + ks) * 2 * 32;
                #pragma unroll
                for (int p = 0; p < 2; p++) {
                    int q = 2 * ks + p;
                    bf[j][p] = Bs[base + p * 32 + (lane ^ (q << 2))];
                }
            }
            #pragma unroll
            for (int i = 0; i < 4; i++)
                #pragma unroll
                for (int j = 0; j < 4; j++)
                    mma_tf32(acc[i][j], af[i], bf[j]);
        }
        __syncthreads();
    }

    const int g = lane >> 2, t = lane & 3;
    #pragma unroll
    for (int i = 0; i < 4; i++) {
        int rbase = m0 + warp_m * 64 + i * 16 + g;
        #pragma unroll
        for (int j = 0; j < 4; j++) {
            int cbase = n0 + warp_n * 32 + j * 8 + t * 2;
            *(float2*)&C[(size_t)rbase * N + cbase] =
                make_float2(acc[i][j][0], acc[i][j][1]);
            *(float2*)&C[(size_t)(rbase + 8) * N + cbase] =
                make_float2(acc[i][j][2], acc[i][j][3]);
        }
    }
}

// ---------------------------------------------------------------------------
// Tensor-core flash attention v4 (tf32, mma.sync).
// Round-5 structure (4 warps, 16 q/warp, 64-key tiles) with:
//   - Q pre-scaled by 1/8 at load (exact power-of-2; kills the scale pass,
//     off-diagonal tiles need no mask pass at all)
//   - PV restructured kg-outer so P fragment is 4 transient regs (not 32)
//   - __launch_bounds__(128,4) to guarantee 4 CTAs/SM
//   - reversed qt order (heavy blocks first)
// ---------------------------------------------------------------------------
__global__ __launch_bounds__(128, 4)
void attn_tc() {
    __shared__ __align__(16) uint32_t Kf[8 * 8 * 2 * 32];
    __shared__ __align__(16) uint32_t Vf[8 * 8 * 2 * 32];

    const int tid  = threadIdx.x;
    const int lane = tid & 31;
    const int w    = tid >> 5;
    const int g    = lane >> 2;
    const int t    = lane & 3;
    const int qt   = (int)(gridDim.x - 1u - blockIdx.x);   // heavy first
    const int h    = blockIdx.y;
    const int b    = blockIdx.z;

    const size_t base = (size_t)b * TT * (3 * D_MODEL);
    const int    hcol = h * DH;
    const int    q0   = qt * 64 + w * 16;

    // Q fragments, pre-scaled by 1/8 (exact)
    uint32_t qf[8][4];
    {
        const float* qA = g_qkv + base + (size_t)(q0 + g) * (3 * D_MODEL) + hcol;
        const float* qB = qA + (size_t)8 * (3 * D_MODEL);
        #pragma unroll
        for (int kg = 0; kg < 8; kg++) {
            qf[kg][0] = f2tf(0.125f * qA[kg * 8 + t]);
            qf[kg][1] = f2tf(0.125f * qB[kg * 8 + t]);
            qf[kg][2] = f2tf(0.125f * qA[kg * 8 + t + 4]);
            qf[kg][3] = f2tf(0.125f * qB[kg * 8 + t + 4]);
        }
    }

    float m0v = -1e30f, m1v = -1e30f, l0 = 0.f, l1 = 0.f;
    float o[8][4];
    #pragma unroll
    for (int nt = 0; nt < 8; nt++)
        #pragma unroll
        for (int e = 0; e < 4; e++) o[nt][e] = 0.f;

    const int src  = (lane & ~3) | (t >> 1);
    const int src2 = src + 2;

    for (int j = 0; j <= qt; j++) {
        __syncthreads();
        // ---- stage K, V tiles (64 keys x 64 d) ----
        #pragma unroll
        for (int it = 0; it < 8; it++) {
            int lin = tid + it * 128;
            int key = (lin & 7) | ((lin >> 7) << 3);
            int c   = (lin >> 3) & 15;
            const float* kvp = g_qkv + base + (size_t)(j * 64 + key) * (3 * D_MODEL)
                               + D_MODEL + hcol + c * 4;
            float4 kv4 = *(const float4*)kvp;
            float4 vv4 = *(const float4*)(kvp + D_MODEL);

            int koff = (((((c >> 1) * 8 + (key >> 3)) * 2) + (c & 1)) << 5) + ((key & 7) << 2);
            *(uint4*)&Kf[koff] = make_uint4(f2tf(kv4.x), f2tf(kv4.y), f2tf(kv4.z), f2tf(kv4.w));

            int kgv  = key >> 3;
            int pv   = (key >> 2) & 1;
            int ntv  = c >> 1;
            int vb   = ((kgv * 8 + ntv) * 2 + pv) << 5;
            int lb   = 16 * (c & 1) + (key & 3);
            int swz  = (4 * (ntv & 1)) ^ (8 * pv);
            float ve[4] = {vv4.x, vv4.y, vv4.z, vv4.w};
            #pragma unroll
            for (int jj = 0; jj < 4; jj++)
                Vf[vb + ((lb + 4 * jj) ^ swz)] = f2tf(ve[jj]);
        }
        __syncthreads();

        const bool diag = (j == qt);
        const int  lim  = diag ? (2 * w + 2) : 8;

        // ---- S = Q K^T (Q pre-scaled) ----
        float s[8][4];
        #pragma unroll
        for (int nt = 0; nt < 8; nt++) {
            if (nt < lim) {
                #pragma unroll
                for (int e = 0; e < 4; e++) s[nt][e] = 0.f;
                #pragma unroll
                for (int kg = 0; kg < 8; kg++) {
                    int kb = ((kg * 8 + nt) * 2) << 5;
                    uint32_t bf[2] = {Kf[kb + lane], Kf[kb + 32 + lane]};
                    mma_tf32(s[nt], qf[kg], bf);
                }
            }
        }

        // ---- causal mask (diagonal tile only; no scale pass needed) ----
        if (diag) {
            #pragma unroll
            for (int nt = 0; nt < 8; nt++) {
                if (nt < lim) {
                    #pragma unroll
                    for (int e = 0; e < 4; e++) {
                        int keyl = nt * 8 + 2 * t + (e & 1);
                        int rowl = w * 16 + g + ((e >> 1) << 3);
                        if (keyl > rowl) s[nt][e] = -1e30f;
                    }
                }
            }
        }

        // ---- online softmax ----
        float rm0 = -1e30f, rm1 = -1e30f;
        #pragma unroll
        for (int nt = 0; nt < 8; nt++) {
            if (nt < lim) {
                rm0 = fmaxf(rm0, fmaxf(s[nt][0], s[nt][1]));
                rm1 = fmaxf(rm1, fmaxf(s[nt][2], s[nt][3]));
            }
        }
        rm0 = fmaxf(rm0, __shfl_xor_sync(0xffffffffu, rm0, 1));
        rm0 = fmaxf(rm0, __shfl_xor_sync(0xffffffffu, rm0, 2));
        rm1 = fmaxf(rm1, __shfl_xor_sync(0xffffffffu, rm1, 1));
        rm1 = fmaxf(rm1, __shfl_xor_sync(0xffffffffu, rm1, 2));

        float mn0 = fmaxf(m0v, rm0), mn1 = fmaxf(m1v, rm1);
        float a0 = __expf(m0v - mn0), a1 = __expf(m1v - mn1);
        m0v = mn0; m1v = mn1;

        float rs0 = 0.f, rs1 = 0.f;
        #pragma unroll
        for (int nt = 0; nt < 8; nt++) {
            if (nt < lim) {
                s[nt][0] = __expf(s[nt][0] - mn0);
                s[nt][1] = __expf(s[nt][1] - mn0);
                s[nt][2] = __expf(s[nt][2] - mn1);
                s[nt][3] = __expf(s[nt][3] - mn1);
                rs0 += s[nt][0] + s[nt][1];
                rs1 += s[nt][2] + s[nt][3];
            }
        }
        rs0 += __shfl_xor_sync(0xffffffffu, rs0, 1);
        rs0 += __shfl_xor_sync(0xffffffffu, rs0, 2);
        rs1 += __shfl_xor_sync(0xffffffffu, rs1, 1);
        rs1 += __shfl_xor_sync(0xffffffffu, rs1, 2);
        l0 = l0 * a0 + rs0;
        l1 = l1 * a1 + rs1;

        #pragma unroll
        for (int nt = 0; nt < 8; nt++) {
            o[nt][0] *= a0; o[nt][1] *= a0;
            o[nt][2] *= a1; o[nt][3] *= a1;
        }

        // ---- PV: kg-outer, transient P fragment (4 regs) ----
        #pragma unroll
        for (int kg = 0; kg < 8; kg++) {
            if (kg < lim) {
                uint32_t c0 = f2tf(s[kg][0]), c1 = f2tf(s[kg][1]);
                uint32_t c2 = f2tf(s[kg][2]), c3 = f2tf(s[kg][3]);
                uint32_t u0 = __shfl_sync(0xffffffffu, c0, src);
                uint32_t u1 = __shfl_sync(0xffffffffu, c1, src);
                uint32_t u2 = __shfl_sync(0xffffffffu, c2, src);
                uint32_t u3 = __shfl_sync(0xffffffffu, c3, src);
                uint32_t v0 = __shfl_sync(0xffffffffu, c0, src2);
                uint32_t v1 = __shfl_sync(0xffffffffu, c1, src2);
                uint32_t v2 = __shfl_sync(0xffffffffu, c2, src2);
                uint32_t v3 = __shfl_sync(0xffffffffu, c3, src2);
                bool odd = (t & 1);
                uint32_t p[4];
                p[0] = odd ? u1 : u0;
                p[1] = odd ? u3 : u2;
                p[2] = odd ? v1 : v0;
                p[3] = odd ? v3 : v2;

                #pragma unroll
                for (int nt = 0; nt < 8; nt++) {
                    int sw0 = 4 * (nt & 1);
                    int vb = ((kg * 8 + nt) * 2) << 5;
                    uint32_t bf[2] = {Vf[vb + (lane ^ sw0)],
                                      Vf[vb + 32 + (lane ^ sw0 ^ 8)]};
                    mma_tf32(o[nt], p, bf);
                }
            }
        }
    }

    float inv0 = 1.f / l0, inv1 = 1.f / l1;
    size_t r0 = (size_t)(b * TT + q0 + g) * D_MODEL + hcol;
    size_t r1 = (size_t)(b * TT + q0 + g + 8) * D_MODEL + hcol;
    #pragma unroll
    for (int nt = 0; nt < 8; nt++) {
        int cb = nt * 8 + 2 * t;
        *(float2*)&g_y[r0 + cb] = make_float2(o[nt][0] * inv0, o[nt][1] * inv0);
        *(float2*)&g_y[r1 + cb] = make_float2(o[nt][2] * inv1, o[nt][3] * inv1);
    }
}

// ---------------------------------------------------------------------------
extern "C" void kernel_launch(void* const* d_in, const int* in_sizes, int n_in,
                              void* d_out, int out_size) {
    const float* x      = (const float*)d_in[0];
    const float* w_qkv  = (const float*)d_in[1];
    const float* w_proj = (const float*)d_in[2];
    float*       out    = (float*)d_out;

    float *qkv_ptr = nullptr, *y_ptr = nullptr;
    cudaGetSymbolAddress((void**)&qkv_ptr, g_qkv);
    cudaGetSymbolAddress((void**)&y_ptr,   g_y);

    gemm_tf32<<<dim3(3 * D_MODEL / 128, BT / 128), 256>>>(x, w_qkv, qkv_ptr,
                                                          BT, 3 * D_MODEL, D_MODEL);

    attn_tc<<<dim3(TT / 64, NH, BB), 128>>>();

    gemm_tf32<<<dim3(D_MODEL / 128, BT / 128), 256>>>(y_ptr, w_proj, out,
                                                      BT, D_MODEL, D_MODEL);
}